// round 15
// baseline (speedup 1.0000x reference)
#include <cuda_runtime.h>
#include <cuda_bf16.h>
#include <math.h>
#include <stdint.h>

#define DIM 1024
#define HIDDEN 2048
#define NE 8
#define TOKENS 2048
#define NSLOT (2*TOKENS)

// ---------------- scratch (static device globals; no runtime alloc) ----------
__device__ int   g_cnt[NE];
__device__ int   g_slots[NE * TOKENS];
__device__ float g_w[NSLOT];

__device__ __nv_bfloat16 g_xhi[(size_t)TOKENS * DIM];
__device__ __nv_bfloat16 g_xlo[(size_t)TOKENS * DIM];
__device__ __nv_bfloat16 g_wfchi[(size_t)NE * HIDDEN * DIM];
__device__ __nv_bfloat16 g_wfclo[(size_t)NE * HIDDEN * DIM];
__device__ __nv_bfloat16 g_wpjhi[(size_t)NE * DIM * HIDDEN];
__device__ __nv_bfloat16 g_wpjlo[(size_t)NE * DIM * HIDDEN];
__device__ __nv_bfloat16 g_h2hi[(size_t)NSLOT * HIDDEN];
__device__ __nv_bfloat16 g_h2lo[(size_t)NSLOT * HIDDEN];

// ---------------- helpers -----------------------------------------------------
__device__ __forceinline__ uint32_t smem_u32(const void* p) {
    uint32_t a;
    asm("{ .reg .u64 t; cvta.to.shared.u64 t, %1; cvt.u32.u64 %0, t; }"
        : "=r"(a) : "l"(p));
    return a;
}
__device__ __forceinline__ uint32_t sw128(uint32_t b) { return b ^ ((b >> 3) & 0x70); }

__device__ __forceinline__ void ldm_x4(uint32_t* r, uint32_t addr) {
    asm volatile("ldmatrix.sync.aligned.m8n8.x4.shared.b16 {%0,%1,%2,%3}, [%4];"
                 : "=r"(r[0]), "=r"(r[1]), "=r"(r[2]), "=r"(r[3]) : "r"(addr));
}
__device__ __forceinline__ void mma_bf16(float* d, const uint32_t* a, const uint32_t* b) {
    asm volatile(
        "mma.sync.aligned.m16n8k16.row.col.f32.bf16.bf16.f32 "
        "{%0,%1,%2,%3}, {%4,%5,%6,%7}, {%8,%9}, {%0,%1,%2,%3};"
        : "+f"(d[0]), "+f"(d[1]), "+f"(d[2]), "+f"(d[3])
        : "r"(a[0]), "r"(a[1]), "r"(a[2]), "r"(a[3]), "r"(b[0]), "r"(b[1]));
}
__device__ __forceinline__ void cp16(uint32_t dst, const void* src, uint32_t srcsize) {
    asm volatile("cp.async.cg.shared.global [%0], [%1], 16, %2;"
                 :: "r"(dst), "l"(src), "r"(srcsize) : "memory");
}
__device__ __forceinline__ void cp_commit() {
    asm volatile("cp.async.commit_group;" ::: "memory");
}
template <int N>
__device__ __forceinline__ void cp_wait() {
    asm volatile("cp.async.wait_group %0;" :: "n"(N) : "memory");
}

// ---------------- zero kernels -------------------------------------------------
__global__ void zero_kernel(float* __restrict__ out, int out_size) {
    int i = blockIdx.x * blockDim.x + threadIdx.x;
    if (i == 0) {
        int n4 = out_size >> 2;
        for (int j = n4 << 2; j < out_size; j++) out[j] = 0.f;
    }
    int n4 = out_size >> 2;
    if (i < n4) ((float4*)out)[i] = make_float4(0.f, 0.f, 0.f, 0.f);
}
__global__ void zero_cnt_kernel() {
    if (threadIdx.x < NE) g_cnt[threadIdx.x] = 0;
}

// ---------------- fp32 -> bf16 hi/lo splits -----------------------------------
#define N4X (TOKENS * DIM / 4)
#define N4W (NE * HIDDEN * DIM / 4)
#define N4WH (N4W / 2)

__device__ __forceinline__ void split_one(const float* __restrict__ src,
                                          __nv_bfloat16* __restrict__ hi,
                                          __nv_bfloat16* __restrict__ lo, int idx) {
    float4 v = ((const float4*)src)[idx];
    __nv_bfloat16 h0 = __float2bfloat16(v.x);
    __nv_bfloat16 h1 = __float2bfloat16(v.y);
    __nv_bfloat16 h2 = __float2bfloat16(v.z);
    __nv_bfloat16 h3 = __float2bfloat16(v.w);
    __nv_bfloat16 l0 = __float2bfloat16(v.x - __bfloat162float(h0));
    __nv_bfloat16 l1 = __float2bfloat16(v.y - __bfloat162float(h1));
    __nv_bfloat16 l2 = __float2bfloat16(v.z - __bfloat162float(h2));
    __nv_bfloat16 l3 = __float2bfloat16(v.w - __bfloat162float(h3));
    __nv_bfloat162* hp = (__nv_bfloat162*)(hi + (size_t)idx * 4);
    __nv_bfloat162* lp = (__nv_bfloat162*)(lo + (size_t)idx * 4);
    hp[0] = __nv_bfloat162(h0, h1); hp[1] = __nv_bfloat162(h2, h3);
    lp[0] = __nv_bfloat162(l0, l1); lp[1] = __nv_bfloat162(l2, l3);
}

// x + W_fc experts 0..3 (needed before fc(0-3))
__global__ void split_xfc03_kernel(const float* __restrict__ x,
                                   const float* __restrict__ Wfc) {
    int base = blockIdx.x * (blockDim.x * 4) + threadIdx.x;
#pragma unroll
    for (int k = 0; k < 4; k++) {
        int i = base + k * blockDim.x;
        if (i >= N4X + N4WH) return;
        if (i < N4X) split_one(x, g_xhi, g_xlo, i);
        else         split_one(Wfc, g_wfchi, g_wfclo, i - N4X);
    }
}
// W_fc experts 4..7
__global__ void split_wfc47_kernel(const float* __restrict__ Wfc) {
    int base = blockIdx.x * (blockDim.x * 4) + threadIdx.x;
#pragma unroll
    for (int k = 0; k < 4; k++) {
        int i = base + k * blockDim.x;
        if (i >= N4WH) return;
        split_one(Wfc, g_wfchi, g_wfclo, N4WH + i);
    }
}
// W_proj (all experts)
__global__ void split_wpj_kernel(const float* __restrict__ Wpj) {
    int base = blockIdx.x * (blockDim.x * 4) + threadIdx.x;
#pragma unroll
    for (int k = 0; k < 4; k++) {
        int i = base + k * blockDim.x;
        if (i >= N4W) return;
        split_one(Wpj, g_wpjhi, g_wpjlo, i);
    }
}

// ---------------- router ------------------------------------------------------
__global__ void router_kernel(const float* __restrict__ x,
                              const float* __restrict__ Wr) {
    int warp = threadIdx.x >> 5;
    int lane = threadIdx.x & 31;
    int t = blockIdx.x * 8 + warp;
    if (t >= TOKENS) return;

    float acc[NE];
#pragma unroll
    for (int e = 0; e < NE; e++) acc[e] = 0.f;
    const float* xr = x + (size_t)t * DIM;
    for (int d = lane; d < DIM; d += 32) {
        float xv = xr[d];
#pragma unroll
        for (int e = 0; e < NE; e++) acc[e] += xv * Wr[e * DIM + d];
    }
#pragma unroll
    for (int e = 0; e < NE; e++) {
#pragma unroll
        for (int o = 16; o > 0; o >>= 1)
            acc[e] += __shfl_xor_sync(0xffffffffu, acc[e], o);
    }
    if (lane == 0) {
        float mx = acc[0];
#pragma unroll
        for (int e = 1; e < NE; e++) mx = fmaxf(mx, acc[e]);
        float p[NE]; float Z = 0.f;
#pragma unroll
        for (int e = 0; e < NE; e++) { p[e] = expf(acc[e] - mx); Z += p[e]; }
        int i1 = 0; float b1 = -1.f;
#pragma unroll
        for (int e = 0; e < NE; e++) if (p[e] > b1) { b1 = p[e]; i1 = e; }
        int i2 = -1; float b2 = -1.f;
#pragma unroll
        for (int e = 0; e < NE; e++) if (e != i1 && p[e] > b2) { b2 = p[e]; i2 = e; }
        float p1 = b1 / Z, p2 = b2 / Z;
        float s = p1 + p2 + 1e-8f;
        int pos1 = atomicAdd(&g_cnt[i1], 1);
        g_slots[i1 * TOKENS + pos1] = 2 * t;
        g_w[2 * t] = p1 / s;
        int pos2 = atomicAdd(&g_cnt[i2], 1);
        g_slots[i2 * TOKENS + pos2] = 2 * t + 1;
        g_w[2 * t + 1] = p2 / s;
    }
}

// ---------------- HMMA grouped GEMM (R11 inner loop, + e_base) ---------------
#define OFF_AHI 0
#define OFF_ALO 16384
#define OFF_BHI 32768
#define OFF_BLO 40960
#define STAGE_BYTES 49152
#define NSTAGE 2
#define SMEM_TOTAL (NSTAGE * STAGE_BYTES)

template <int K, int NTOT, int MODE>
__global__ void __launch_bounds__(256, 2) moe_mma_gemm(float* __restrict__ out,
                                                       int e_base) {
    const int e = e_base + blockIdx.z;
    const int cnt = g_cnt[e];
    const int m0 = blockIdx.y * 128;
    if (m0 >= cnt) return;
    const int n0 = blockIdx.x * 64;
    const int* slots = g_slots + e * TOKENS;

    extern __shared__ char smem[];
    const uint32_t sb = smem_u32(smem);
    const int tid = threadIdx.x;
    const int lane = tid & 31;
    const int wid = tid >> 5;
    const int wm = wid & 3;
    const int wn = wid >> 2;

    const __nv_bfloat16* Ahi_base = (MODE == 0) ? g_xhi : g_h2hi;
    const __nv_bfloat16* Alo_base = (MODE == 0) ? g_xlo : g_h2lo;
    const __nv_bfloat16* Bhi_base = (MODE == 0) ? g_wfchi : g_wpjhi;
    const __nv_bfloat16* Blo_base = (MODE == 0) ? g_wfclo : g_wpjlo;

    const int c16 = tid & 7;
    const int r0l = tid >> 3;

    const __nv_bfloat16* aphi[4];
    const __nv_bfloat16* aplo[4];
    uint32_t asz[4];
    uint32_t aoff[4];
#pragma unroll
    for (int p = 0; p < 4; p++) {
        int row = r0l + 32 * p;
        aoff[p] = sw128((uint32_t)(row * 128 + c16 * 16));
        int m = m0 + row;
        if (m < cnt) {
            int slot = slots[m];
            int arow = (MODE == 0) ? (slot >> 1) : slot;
            aphi[p] = Ahi_base + (size_t)arow * K + c16 * 8;
            aplo[p] = Alo_base + (size_t)arow * K + c16 * 8;
            asz[p] = 16u;
        } else {
            aphi[p] = Ahi_base; aplo[p] = Alo_base; asz[p] = 0u;
        }
    }
    const __nv_bfloat16* bphi[2];
    const __nv_bfloat16* bplo[2];
    uint32_t boffs[2];
#pragma unroll
    for (int p = 0; p < 2; p++) {
        int row = r0l + 32 * p;
        boffs[p] = sw128((uint32_t)(row * 128 + c16 * 16));
        size_t bo = ((size_t)e * NTOT + n0 + row) * K + c16 * 8;
        bphi[p] = Bhi_base + bo;
        bplo[p] = Blo_base + bo;
    }

    const uint32_t a_row = wm * 32 + (lane & 15);
    const uint32_t a_kb = (uint32_t)((lane >> 4) << 4);
    const uint32_t b_row = wn * 32 + (lane & 7) + ((lane >> 4) << 3);
    const uint32_t b_kb = (uint32_t)(((lane >> 3) & 1) << 4);

    float acc[2][4][4];
#pragma unroll
    for (int i = 0; i < 2; i++)
#pragma unroll
        for (int j = 0; j < 4; j++)
#pragma unroll
            for (int q = 0; q < 4; q++) acc[i][j][q] = 0.f;

    constexpr int NK = K / 64;
    const int phase = ((blockIdx.x + blockIdx.y) & 1) ? (NK / 2) : 0;

    auto issue = [&](int slab) {
        uint32_t base = sb + (slab & 1) * STAGE_BYTES;
        int kn = slab * 64;
#pragma unroll
        for (int p = 0; p < 4; p++) {
            cp16(base + OFF_AHI + aoff[p], aphi[p] + kn, asz[p]);
            cp16(base + OFF_ALO + aoff[p], aplo[p] + kn, asz[p]);
        }
#pragma unroll
        for (int p = 0; p < 2; p++) {
            cp16(base + OFF_BHI + boffs[p], bphi[p] + kn, 16u);
            cp16(base + OFF_BLO + boffs[p], bplo[p] + kn, 16u);
        }
        cp_commit();
    };

    issue(phase);

    for (int kt = 0; kt < NK; kt++) {
        const int s = (kt + phase) & (NK - 1);
        cp_wait<0>();
        __syncthreads();
        if (kt + 1 < NK) issue((kt + 1 + phase) & (NK - 1));

        const uint32_t base = sb + (s & 1) * STAGE_BYTES;
#pragma unroll
        for (int c = 0; c < 4; c++) {
            const uint32_t kb = (uint32_t)(c * 32);
            uint32_t ah[2][4], al[2][4], bh[2][4], bl[2][4];
#pragma unroll
            for (int i = 0; i < 2; i++) {
                uint32_t off = sw128((a_row + 16 * i) * 128 + kb + a_kb);
                ldm_x4(ah[i], base + OFF_AHI + off);
                ldm_x4(al[i], base + OFF_ALO + off);
            }
#pragma unroll
            for (int jj = 0; jj < 2; jj++) {
                uint32_t off = sw128((b_row + 16 * jj) * 128 + kb + b_kb);
                ldm_x4(bh[jj], base + OFF_BHI + off);
                ldm_x4(bl[jj], base + OFF_BLO + off);
            }
#pragma unroll
            for (int i = 0; i < 2; i++)
#pragma unroll
                for (int j = 0; j < 4; j++)
                    mma_bf16(acc[i][j], ah[i], &bh[j >> 1][(j & 1) * 2]);
#pragma unroll
            for (int i = 0; i < 2; i++)
#pragma unroll
                for (int j = 0; j < 4; j++)
                    mma_bf16(acc[i][j], ah[i], &bl[j >> 1][(j & 1) * 2]);
#pragma unroll
            for (int i = 0; i < 2; i++)
#pragma unroll
                for (int j = 0; j < 4; j++)
                    mma_bf16(acc[i][j], al[i], &bh[j >> 1][(j & 1) * 2]);
        }
    }

    const int gid = lane >> 2;
    const int tig = lane & 3;
#pragma unroll
    for (int i = 0; i < 2; i++) {
#pragma unroll
        for (int h = 0; h < 2; h++) {
            int mrow = m0 + wm * 32 + i * 16 + gid + 8 * h;
            if (mrow >= cnt) continue;
            int slot = slots[mrow];
            if (MODE == 0) {
                __nv_bfloat16* hr = g_h2hi + (size_t)slot * HIDDEN + n0;
                __nv_bfloat16* lr = g_h2lo + (size_t)slot * HIDDEN + n0;
#pragma unroll
                for (int j = 0; j < 4; j++) {
                    int col = wn * 32 + j * 8 + 2 * tig;
                    float v0 = acc[i][j][h * 2 + 0];
                    float v1 = acc[i][j][h * 2 + 1];
                    v0 = fmaxf(v0, 0.f); v0 = v0 * v0;
                    v1 = fmaxf(v1, 0.f); v1 = v1 * v1;
                    __nv_bfloat16 h0 = __float2bfloat16(v0);
                    __nv_bfloat16 h1 = __float2bfloat16(v1);
                    __nv_bfloat16 l0 = __float2bfloat16(v0 - __bfloat162float(h0));
                    __nv_bfloat16 l1 = __float2bfloat16(v1 - __bfloat162float(h1));
                    *(__nv_bfloat162*)(hr + col) = __nv_bfloat162(h0, h1);
                    *(__nv_bfloat162*)(lr + col) = __nv_bfloat162(l0, l1);
                }
            } else {
                float wgt = g_w[slot];
                int token = slot >> 1;
                float* orow = out + (size_t)token * DIM + n0;
#pragma unroll
                for (int j = 0; j < 4; j++) {
                    int col = wn * 32 + j * 8 + 2 * tig;
                    atomicAdd(&orow[col + 0], wgt * acc[i][j][h * 2 + 0]);
                    atomicAdd(&orow[col + 1], wgt * acc[i][j][h * 2 + 1]);
                }
            }
        }
    }
}

// ---------------- launch (half-split overlapped DAG, graph-capturable) --------
extern "C" void kernel_launch(void* const* d_in, const int* in_sizes, int n_in,
                              void* d_out, int out_size) {
    const float* x = (const float*)d_in[0];
    const float* Wr = (const float*)d_in[1];
    const float* Wfc = (const float*)d_in[2];
    const float* Wpj = (const float*)d_in[3];
    float* out = (float*)d_out;

    static cudaStream_t s2 = nullptr;
    static cudaEvent_t evFork = nullptr, evRouter = nullptr, evB = nullptr,
                       evWpj = nullptr, evFc03 = nullptr, evProj03 = nullptr;
    if (s2 == nullptr) {
        cudaStreamCreateWithFlags(&s2, cudaStreamNonBlocking);
        cudaEventCreateWithFlags(&evFork, cudaEventDisableTiming);
        cudaEventCreateWithFlags(&evRouter, cudaEventDisableTiming);
        cudaEventCreateWithFlags(&evB, cudaEventDisableTiming);
        cudaEventCreateWithFlags(&evWpj, cudaEventDisableTiming);
        cudaEventCreateWithFlags(&evFc03, cudaEventDisableTiming);
        cudaEventCreateWithFlags(&evProj03, cudaEventDisableTiming);
        cudaFuncSetAttribute(moe_mma_gemm<DIM, HIDDEN, 0>,
                             cudaFuncAttributeMaxDynamicSharedMemorySize, SMEM_TOTAL);
        cudaFuncSetAttribute(moe_mma_gemm<HIDDEN, DIM, 1>,
                             cudaFuncAttributeMaxDynamicSharedMemorySize, SMEM_TOTAL);
    }

    // main: counter zero (router dep), fork side stream
    zero_cnt_kernel<<<1, 32>>>();
    cudaEventRecord(evFork, 0);
    cudaStreamWaitEvent(s2, evFork, 0);

    // side: router -> zero(out) -> split W_fc[4..7] -> split W_proj
    router_kernel<<<TOKENS / 8, 256, 0, s2>>>(x, Wr);
    cudaEventRecord(evRouter, s2);
    zero_kernel<<<(out_size / 4 + 255) / 256, 256, 0, s2>>>(out, out_size);
    split_wfc47_kernel<<<(N4WH + 1023) / 1024, 256, 0, s2>>>(Wfc);
    cudaEventRecord(evB, s2);
    split_wpj_kernel<<<(N4W + 1023) / 1024, 256, 0, s2>>>(Wpj);
    cudaEventRecord(evWpj, s2);

    // main: split x + W_fc[0..3] (concurrent with side stream)
    split_xfc03_kernel<<<(N4X + N4WH + 1023) / 1024, 256>>>(x, Wfc);

    // fc(0-3): needs router + split_xfc03
    cudaStreamWaitEvent(0, evRouter, 0);
    moe_mma_gemm<DIM, HIDDEN, 0>
        <<<dim3(HIDDEN / 64, TOKENS / 128, 4), 256, SMEM_TOTAL>>>(out, 0);
    cudaEventRecord(evFc03, 0);

    // fc(4-7): needs W_fc[4..7] split
    cudaStreamWaitEvent(0, evB, 0);
    moe_mma_gemm<DIM, HIDDEN, 0>
        <<<dim3(HIDDEN / 64, TOKENS / 128, 4), 256, SMEM_TOTAL>>>(out, 4);

    // side: proj(0-3) overlaps fc(4-7). Needs fc03 + zero + W_proj split
    // (zero and split_wpj precede in s2 program order).
    cudaStreamWaitEvent(s2, evFc03, 0);
    moe_mma_gemm<HIDDEN, DIM, 1>
        <<<dim3(DIM / 64, TOKENS / 128, 4), 256, SMEM_TOTAL, s2>>>(out, 0);
    cudaEventRecord(evProj03, s2);

    // main: proj(4-7) after fc(4-7) (program order) + zero/W_proj split
    cudaStreamWaitEvent(0, evWpj, 0);
    moe_mma_gemm<HIDDEN, DIM, 1>
        <<<dim3(DIM / 64, TOKENS / 128, 4), 256, SMEM_TOTAL>>>(out, 4);

    // join side stream
    cudaStreamWaitEvent(0, evProj03, 0);
}